// round 4
// baseline (speedup 1.0000x reference)
#include <cuda_runtime.h>
#include <math.h>

#define N_NODES 100000
#define F_IN    512
#define HID     128
#define CLS     64

// ---------------- scratch (no cudaMalloc allowed) ----------------
__device__ float g_h1 [(size_t)N_NODES * HID];   // g1 = inv*(x@W1), later relu activations a1
__device__ float g_acc1[(size_t)N_NODES * HID];  // layer-1 accumulator
__device__ float g_h2 [(size_t)N_NODES * CLS];   // g2 = inv*(a1@W2)
__device__ float g_inv[N_NODES];
__device__ int   g_deg[N_NODES];

// ---------------- degree ----------------
__global__ void k_init_deg() {
    int i = blockIdx.x * blockDim.x + threadIdx.x;
    if (i < N_NODES) g_deg[i] = 1;               // self-loop
}

__global__ void k_deg(const int* __restrict__ dst, int E) {
    int i = blockIdx.x * blockDim.x + threadIdx.x;
    int stride = gridDim.x * blockDim.x;
    for (; i < E; i += stride) atomicAdd(&g_deg[dst[i]], 1);
}

__global__ void k_inv() {
    int i = blockIdx.x * blockDim.x + threadIdx.x;
    if (i < N_NODES) g_inv[i] = rsqrtf((float)g_deg[i]);
}

// ---------------- SGEMM with inv-scale epilogue, dual store ----------------
// LAYER==1: C = inv[row]*(A @ W1), written to g_h1 and g_acc1.
// LAYER==2: C = inv[row]*(g_h1 @ W2), written to g_h2 and ACC2 (harness out).
template<int BM, int BN, int BK, int TM, int TN, int LAYER>
__global__ __launch_bounds__((BM/TM)*(BN/TN))
void k_sgemm(const float* __restrict__ Ain, const float* __restrict__ B,
             float* __restrict__ ACC2, int M, int N, int K)
{
    constexpr int THREADS = (BM/TM)*(BN/TN);
    __shared__ float As[BK][BM + 4];
    __shared__ float Bs[BK][BN];

    const float* A   = (LAYER == 1) ? Ain : (const float*)g_h1;
    float*       G   = (LAYER == 1) ? (float*)g_h1  : (float*)g_h2;
    float*       ACC = (LAYER == 1) ? (float*)g_acc1 : ACC2;

    const int tid = threadIdx.x;
    const int tx  = tid % (BN/TN);
    const int ty  = tid / (BN/TN);
    const int rowBase = blockIdx.x * BM;
    const int colBase = blockIdx.y * BN;

    float acc[TM][TN] = {};

    for (int k0 = 0; k0 < K; k0 += BK) {
        #pragma unroll
        for (int i = 0; i < BM*BK/4/THREADS; i++) {
            int id = tid + i*THREADS;
            int m  = id / (BK/4);
            int k4 = id % (BK/4);
            int row = rowBase + m;
            float4 v = (row < M) ? *(const float4*)(A + (size_t)row*K + k0 + k4*4)
                                 : make_float4(0.f,0.f,0.f,0.f);
            As[k4*4+0][m] = v.x; As[k4*4+1][m] = v.y;
            As[k4*4+2][m] = v.z; As[k4*4+3][m] = v.w;
        }
        #pragma unroll
        for (int i = 0; i < BK*BN/4/THREADS; i++) {
            int id = tid + i*THREADS;
            int kk = id / (BN/4);
            int n4 = id % (BN/4);
            *(float4*)&Bs[kk][n4*4] = *(const float4*)(B + (size_t)(k0+kk)*N + colBase + n4*4);
        }
        __syncthreads();

        #pragma unroll
        for (int kk = 0; kk < BK; kk++) {
            float am[TM], bn[TN];
            #pragma unroll
            for (int i = 0; i < TM; i += 4)
                *(float4*)&am[i] = *(const float4*)&As[kk][ty*TM + i];
            #pragma unroll
            for (int j = 0; j < TN; j += 4)
                *(float4*)&bn[j] = *(const float4*)&Bs[kk][tx*TN + j];
            #pragma unroll
            for (int i = 0; i < TM; i++)
                #pragma unroll
                for (int j = 0; j < TN; j++)
                    acc[i][j] = fmaf(am[i], bn[j], acc[i][j]);
        }
        __syncthreads();
    }

    #pragma unroll
    for (int i = 0; i < TM; i++) {
        int row = rowBase + ty*TM + i;
        if (row >= M) continue;
        float s = g_inv[row];
        #pragma unroll
        for (int j = 0; j < TN; j += 4) {
            float4 v;
            v.x = acc[i][j+0]*s; v.y = acc[i][j+1]*s;
            v.z = acc[i][j+2]*s; v.w = acc[i][j+3]*s;
            size_t off = (size_t)row*N + colBase + tx*TN + j;
            *(float4*)(G + off)   = v;
            *(float4*)(ACC + off) = v;   // accumulator seeded with self-loop term
        }
    }
}

// ---------------- edge scatter: acc[dst] += g[src] ----------------
__global__ void k_scatter128(const int* __restrict__ src,
                             const int* __restrict__ dst, int E)
{
    int lane = threadIdx.x & 31;
    int w    = (blockIdx.x * blockDim.x + threadIdx.x) >> 5;
    int nw   = (gridDim.x * blockDim.x) >> 5;
    for (int e = w; e < E; e += nw) {
        int s = src[e];
        int d = dst[e];
        float4 v = *(const float4*)((const float*)g_h1 + (size_t)s*HID + lane*4);
        float* a = (float*)g_acc1 + (size_t)d*HID + lane*4;
        atomicAdd(a+0, v.x); atomicAdd(a+1, v.y);
        atomicAdd(a+2, v.z); atomicAdd(a+3, v.w);
    }
}

__global__ void k_scatter64(const int* __restrict__ src,
                            const int* __restrict__ dst,
                            float* __restrict__ acc, int E)
{
    int lane = threadIdx.x & 31;
    int w    = (blockIdx.x * blockDim.x + threadIdx.x) >> 5;
    int nw   = (gridDim.x * blockDim.x) >> 5;
    for (int e = w; e < E; e += nw) {
        int s = src[e];
        int d = dst[e];
        float2 v = *(const float2*)((const float*)g_h2 + (size_t)s*CLS + lane*2);
        float* a = acc + (size_t)d*CLS + lane*2;
        atomicAdd(a+0, v.x); atomicAdd(a+1, v.y);
    }
}

// ---------------- layer-1 finalize: a1 = relu(inv*acc + b1) ----------------
__global__ void k_finalize1(const float* __restrict__ b1) {
    int i = blockIdx.x * blockDim.x + threadIdx.x;
    if (i >= N_NODES * HID) return;
    int v = i / HID, f = i % HID;
    float val = g_inv[v] * g_acc1[i] + b1[f];
    g_h1[i] = fmaxf(val, 0.f);
}

// ---------------- layer-2 finalize: log_softmax(inv*acc + b2), in place ----
__global__ void k_lsm(float* __restrict__ out, const float* __restrict__ b2) {
    int w    = (blockIdx.x * blockDim.x + threadIdx.x) >> 5;
    int lane = threadIdx.x & 31;
    if (w >= N_NODES) return;
    float2 a = *(const float2*)(out + (size_t)w*CLS + lane*2);
    float s  = g_inv[w];
    float t0 = s*a.x + b2[lane*2+0];
    float t1 = s*a.y + b2[lane*2+1];
    float m = fmaxf(t0, t1);
    #pragma unroll
    for (int o = 16; o > 0; o >>= 1) m = fmaxf(m, __shfl_xor_sync(0xffffffffu, m, o));
    float sum = __expf(t0 - m) + __expf(t1 - m);
    #pragma unroll
    for (int o = 16; o > 0; o >>= 1) sum += __shfl_xor_sync(0xffffffffu, sum, o);
    float ls = m + __logf(sum);
    float2 r; r.x = t0 - ls; r.y = t1 - ls;
    *(float2*)(out + (size_t)w*CLS + lane*2) = r;
}

// ---------------- launch ----------------
extern "C" void kernel_launch(void* const* d_in, const int* in_sizes, int n_in,
                              void* d_out, int out_size)
{
    const float* x   = (const float*)d_in[0];
    const int*   src = (const int*)d_in[1];     // JAX default x64 disabled -> int32
    const int*   dst = (const int*)d_in[2];
    const float* W1  = (const float*)d_in[3];
    const float* b1  = (const float*)d_in[4];
    const float* W2  = (const float*)d_in[5];
    const float* b2  = (const float*)d_in[6];
    float* out = (float*)d_out;
    const int E = in_sizes[1];

    // degree + normalization
    k_init_deg<<<(N_NODES + 255)/256, 256>>>();
    k_deg<<<4096, 256>>>(dst, E);
    k_inv<<<(N_NODES + 255)/256, 256>>>();

    // layer 1: g1 = inv*(x@W1) -> scatter -> relu(inv*acc + b1)
    dim3 grid1((N_NODES + 127)/128, HID/128);
    k_sgemm<128,128,16,8,8,1><<<grid1, 256>>>(x, W1, nullptr, N_NODES, HID, F_IN);
    k_scatter128<<<4096, 256>>>(src, dst, E);
    k_finalize1<<<(N_NODES*HID + 255)/256, 256>>>(b1);

    // layer 2: g2 = inv*(a1@W2) -> scatter into d_out -> log_softmax
    dim3 grid2((N_NODES + 127)/128, CLS/64);
    k_sgemm<128,64,16,8,4,2><<<grid2, 256>>>(nullptr, W2, out, N_NODES, CLS, HID);
    k_scatter64<<<4096, 256>>>(src, dst, out, E);
    k_lsm<<<(N_NODES*32 + 255)/256, 256>>>(out, b2);
}

// round 5
// speedup vs baseline: 1.8722x; 1.8722x over previous
#include <cuda_runtime.h>
#include <math.h>
#include <stdint.h>

#define N_NODES 100000
#define F_IN    512
#define HID     128
#define CLS     64

// ---------------- scratch (no cudaMalloc allowed) ----------------
__device__ float g_h1 [(size_t)N_NODES * HID];   // g1 = inv*(x@W1), later relu activations a1
__device__ float g_acc1[(size_t)N_NODES * HID];  // layer-1 accumulator
__device__ float g_h2 [(size_t)N_NODES * CLS];   // g2 = inv*(a1@W2)
__device__ float g_inv[N_NODES];
__device__ int   g_deg[N_NODES];

// ---------------- degree ----------------
__global__ void k_init_deg() {
    int i = blockIdx.x * blockDim.x + threadIdx.x;
    if (i < N_NODES) g_deg[i] = 1;               // self-loop
}

__global__ void k_deg(const int* __restrict__ dst, int E) {
    int i = blockIdx.x * blockDim.x + threadIdx.x;
    int stride = gridDim.x * blockDim.x;
    for (; i < E; i += stride) atomicAdd(&g_deg[dst[i]], 1);
}

__global__ void k_inv() {
    int i = blockIdx.x * blockDim.x + threadIdx.x;
    if (i < N_NODES) g_inv[i] = rsqrtf((float)g_deg[i]);
}

// ---------------- tf32 helpers ----------------
__device__ __forceinline__ uint32_t f2tf32(float f) {
    uint32_t r;
    asm("cvt.rna.tf32.f32 %0, %1;" : "=r"(r) : "f"(f));
    return r;
}

__device__ __forceinline__ void mma_tf32(float* c, uint32_t a0, uint32_t a1,
                                         uint32_t a2, uint32_t a3,
                                         uint32_t b0, uint32_t b1) {
    asm volatile(
        "mma.sync.aligned.m16n8k8.row.col.f32.tf32.tf32.f32 "
        "{%0,%1,%2,%3}, {%4,%5,%6,%7}, {%8,%9}, {%0,%1,%2,%3};"
        : "+f"(c[0]), "+f"(c[1]), "+f"(c[2]), "+f"(c[3])
        : "r"(a0), "r"(a1), "r"(a2), "r"(a3), "r"(b0), "r"(b1));
}

// ---------------- tf32 tensor-core GEMM, inv-scale epilogue, dual store ---
// LAYER==1: C = inv[row]*(A @ W1) -> g_h1 and g_acc1.    (N=HID=128)
// LAYER==2: C = inv[row]*(g_h1 @ W2) -> g_h2 and ACC2.   (N=CLS=64)
// 256 threads = 8 warps. Each warp: WM rows x 64 cols (8 n-tiles of m16n8k8).
template<int BM, int BN, int BK, int LAYER>
__global__ __launch_bounds__(256)
void k_mma(const float* __restrict__ Ain, const float* __restrict__ B,
           float* __restrict__ ACC2, int M, int K)
{
    constexpr int WARPS_N = BN / 64;            // 2 (L1) or 1 (L2)
    constexpr int WARPS_M = 8 / WARPS_N;        // 4 or 8
    constexpr int WM      = BM / WARPS_M;       // 32 or 16
    constexpr int RT      = WM / 16;            // 2 or 1
    constexpr int ASTR    = BK + 4;             // 36: banks (4g+tg) conflict-free
    constexpr int BSTR    = BN + 8;             // 136/72: banks (8tg+g) conflict-free

    __shared__ float As[BM][ASTR];
    __shared__ float Bs[BK][BSTR];

    const float* A   = (LAYER == 1) ? Ain : (const float*)g_h1;
    float*       G   = (LAYER == 1) ? (float*)g_h1  : (float*)g_h2;
    float*       ACC = (LAYER == 1) ? (float*)g_acc1 : ACC2;
    const int    N   = BN;                      // grid.y == 1 (BN == full width)

    const int tid  = threadIdx.x;
    const int warp = tid >> 5;
    const int lane = tid & 31;
    const int g    = lane >> 2;                 // 0..7
    const int tg   = lane & 3;                  // 0..3
    const int wr   = (warp / WARPS_N) * WM;
    const int wc   = (warp % WARPS_N) * 64;
    const int rowBase = blockIdx.x * BM;

    float acc[RT][8][4] = {};

    for (int k0 = 0; k0 < K; k0 += BK) {
        // A tile: BM x BK, float4 loads, tf32-convert, float4 STS
        #pragma unroll
        for (int i = 0; i < BM*BK/4/256; i++) {
            int id = tid + i*256;
            int m  = id / (BK/4);
            int k4 = id % (BK/4);
            int row = rowBase + m;
            float4 v = (row < M) ? *(const float4*)(A + (size_t)row*K + k0 + k4*4)
                                 : make_float4(0.f,0.f,0.f,0.f);
            float4 t;
            t.x = __uint_as_float(f2tf32(v.x));
            t.y = __uint_as_float(f2tf32(v.y));
            t.z = __uint_as_float(f2tf32(v.z));
            t.w = __uint_as_float(f2tf32(v.w));
            *(float4*)&As[m][k4*4] = t;
        }
        // B tile: BK x BN
        #pragma unroll
        for (int i = 0; i < BK*BN/4/256; i++) {
            int id = tid + i*256;
            int kk = id / (BN/4);
            int n4 = id % (BN/4);
            float4 v = *(const float4*)(B + (size_t)(k0+kk)*N + n4*4);
            float4 t;
            t.x = __uint_as_float(f2tf32(v.x));
            t.y = __uint_as_float(f2tf32(v.y));
            t.z = __uint_as_float(f2tf32(v.z));
            t.w = __uint_as_float(f2tf32(v.w));
            *(float4*)&Bs[kk][n4*4] = t;
        }
        __syncthreads();

        #pragma unroll
        for (int ks = 0; ks < BK/8; ks++) {
            int k = ks*8;
            uint32_t bf[8][2];
            #pragma unroll
            for (int j = 0; j < 8; j++) {
                bf[j][0] = __float_as_uint(Bs[k+tg  ][wc + j*8 + g]);
                bf[j][1] = __float_as_uint(Bs[k+tg+4][wc + j*8 + g]);
            }
            #pragma unroll
            for (int rt = 0; rt < RT; rt++) {
                int r = wr + rt*16;
                uint32_t a0 = __float_as_uint(As[r+g  ][k+tg  ]);
                uint32_t a1 = __float_as_uint(As[r+g+8][k+tg  ]);
                uint32_t a2 = __float_as_uint(As[r+g  ][k+tg+4]);
                uint32_t a3 = __float_as_uint(As[r+g+8][k+tg+4]);
                #pragma unroll
                for (int j = 0; j < 8; j++)
                    mma_tf32(acc[rt][j], a0, a1, a2, a3, bf[j][0], bf[j][1]);
            }
        }
        __syncthreads();
    }

    // epilogue: scale by inv[row], dual store (float2 per fragment half)
    #pragma unroll
    for (int rt = 0; rt < RT; rt++) {
        int r0 = rowBase + wr + rt*16 + g;
        int r1 = r0 + 8;
        float s0 = (r0 < M) ? g_inv[r0] : 0.f;
        float s1 = (r1 < M) ? g_inv[r1] : 0.f;
        #pragma unroll
        for (int j = 0; j < 8; j++) {
            int col = wc + j*8 + tg*2;
            if (r0 < M) {
                float2 v; v.x = acc[rt][j][0]*s0; v.y = acc[rt][j][1]*s0;
                size_t off = (size_t)r0*N + col;
                *(float2*)(G + off) = v;
                *(float2*)(ACC + off) = v;
            }
            if (r1 < M) {
                float2 v; v.x = acc[rt][j][2]*s1; v.y = acc[rt][j][3]*s1;
                size_t off = (size_t)r1*N + col;
                *(float2*)(G + off) = v;
                *(float2*)(ACC + off) = v;
            }
        }
    }
}

// ---------------- edge scatter: acc[dst] += g[src] ----------------
__global__ void k_scatter128(const int* __restrict__ src,
                             const int* __restrict__ dst, int E)
{
    int lane = threadIdx.x & 31;
    int w    = (blockIdx.x * blockDim.x + threadIdx.x) >> 5;
    int nw   = (gridDim.x * blockDim.x) >> 5;
    for (int e = w; e < E; e += nw) {
        int s = src[e];
        int d = dst[e];
        float4 v = *(const float4*)((const float*)g_h1 + (size_t)s*HID + lane*4);
        float* a = (float*)g_acc1 + (size_t)d*HID + lane*4;
        asm volatile("red.global.add.v4.f32 [%0], {%1,%2,%3,%4};"
                     :: "l"(a), "f"(v.x), "f"(v.y), "f"(v.z), "f"(v.w) : "memory");
    }
}

__global__ void k_scatter64(const int* __restrict__ src,
                            const int* __restrict__ dst,
                            float* __restrict__ acc, int E)
{
    int lane = threadIdx.x & 31;
    int w    = (blockIdx.x * blockDim.x + threadIdx.x) >> 5;
    int nw   = (gridDim.x * blockDim.x) >> 5;
    for (int e = w; e < E; e += nw) {
        int s = src[e];
        int d = dst[e];
        float2 v = *(const float2*)((const float*)g_h2 + (size_t)s*CLS + lane*2);
        float* a = acc + (size_t)d*CLS + lane*2;
        asm volatile("red.global.add.v2.f32 [%0], {%1,%2};"
                     :: "l"(a), "f"(v.x), "f"(v.y) : "memory");
    }
}

// ---------------- layer-1 finalize: a1 = relu(inv*acc + b1) ----------------
__global__ void k_finalize1(const float* __restrict__ b1) {
    int i = blockIdx.x * blockDim.x + threadIdx.x;
    if (i >= N_NODES * HID) return;
    int v = i / HID, f = i % HID;
    float val = g_inv[v] * g_acc1[i] + b1[f];
    g_h1[i] = fmaxf(val, 0.f);
}

// ---------------- layer-2 finalize: log_softmax(inv*acc + b2), in place ----
__global__ void k_lsm(float* __restrict__ out, const float* __restrict__ b2) {
    int w    = (blockIdx.x * blockDim.x + threadIdx.x) >> 5;
    int lane = threadIdx.x & 31;
    if (w >= N_NODES) return;
    float2 a = *(const float2*)(out + (size_t)w*CLS + lane*2);
    float s  = g_inv[w];
    float t0 = s*a.x + b2[lane*2+0];
    float t1 = s*a.y + b2[lane*2+1];
    float m = fmaxf(t0, t1);
    #pragma unroll
    for (int o = 16; o > 0; o >>= 1) m = fmaxf(m, __shfl_xor_sync(0xffffffffu, m, o));
    float sum = __expf(t0 - m) + __expf(t1 - m);
    #pragma unroll
    for (int o = 16; o > 0; o >>= 1) sum += __shfl_xor_sync(0xffffffffu, sum, o);
    float ls = m + __logf(sum);
    float2 r; r.x = t0 - ls; r.y = t1 - ls;
    *(float2*)(out + (size_t)w*CLS + lane*2) = r;
}

// ---------------- launch ----------------
extern "C" void kernel_launch(void* const* d_in, const int* in_sizes, int n_in,
                              void* d_out, int out_size)
{
    const float* x   = (const float*)d_in[0];
    const int*   src = (const int*)d_in[1];     // JAX default x64 disabled -> int32
    const int*   dst = (const int*)d_in[2];
    const float* W1  = (const float*)d_in[3];
    const float* b1  = (const float*)d_in[4];
    const float* W2  = (const float*)d_in[5];
    const float* b2  = (const float*)d_in[6];
    float* out = (float*)d_out;
    const int E = in_sizes[1];

    // degree + normalization
    k_init_deg<<<(N_NODES + 255)/256, 256>>>();
    k_deg<<<4096, 256>>>(dst, E);
    k_inv<<<(N_NODES + 255)/256, 256>>>();

    const int gx = (N_NODES + 127)/128;

    // layer 1: g1 = inv*(x@W1) -> scatter -> relu(inv*acc + b1)
    k_mma<128,128,32,1><<<gx, 256>>>(x, W1, nullptr, N_NODES, F_IN);
    k_scatter128<<<4096, 256>>>(src, dst, E);
    k_finalize1<<<(N_NODES*HID + 255)/256, 256>>>(b1);

    // layer 2: g2 = inv*(a1@W2) -> scatter into d_out -> log_softmax
    k_mma<128,64,32,2><<<gx, 256>>>(nullptr, W2, out, N_NODES, HID);
    k_scatter64<<<4096, 256>>>(src, dst, out, E);
    k_lsm<<<(N_NODES*32 + 255)/256, 256>>>(out, b2);
}

// round 6
// speedup vs baseline: 3.6251x; 1.9363x over previous
#include <cuda_runtime.h>
#include <math.h>
#include <stdint.h>

#define N_NODES 100000
#define F_IN    512
#define HID     128
#define CLS     64
#define E_MAX   1600000

// ---------------- scratch (no cudaMalloc allowed) ----------------
__device__ float g_h1  [(size_t)N_NODES * HID];  // g1 = inv*(x@W1)
__device__ float g_acc1[(size_t)N_NODES * HID];  // a1 = relu(inv*sum + b1)
__device__ float g_h2  [(size_t)N_NODES * CLS];  // g2 = inv*(a1@W2)
__device__ float g_inv [N_NODES];
__device__ int   g_cnt [N_NODES];
__device__ int   g_rowstart[N_NODES + 1];
__device__ int   g_cursor[N_NODES];
__device__ int   g_blksum[256];
__device__ int   g_blkoff[256];
__device__ int   g_esrc[E_MAX];

// ---------------- degree histogram + inv sqrt ----------------
__global__ void k_zero() {
    int i = blockIdx.x * blockDim.x + threadIdx.x;
    if (i < N_NODES) g_cnt[i] = 0;
}
__global__ void k_hist(const int* __restrict__ dst, int E) {
    int i = blockIdx.x * blockDim.x + threadIdx.x;
    if (i < E) atomicAdd(&g_cnt[dst[i]], 1);
}
__global__ void k_inv() {
    int i = blockIdx.x * blockDim.x + threadIdx.x;
    if (i < N_NODES) g_inv[i] = rsqrtf((float)(1 + g_cnt[i]));  // +1 self-loop
}

// ---------------- exclusive scan over g_cnt (3 kernels) ----------------
#define SCB 512
__global__ void k_scan1(int n) {
    __shared__ int sm[SCB];
    int i = blockIdx.x * SCB + threadIdx.x;
    int v = (i < n) ? g_cnt[i] : 0;
    sm[threadIdx.x] = v; __syncthreads();
    #pragma unroll
    for (int o = 1; o < SCB; o <<= 1) {
        int t = (threadIdx.x >= o) ? sm[threadIdx.x - o] : 0;
        __syncthreads(); sm[threadIdx.x] += t; __syncthreads();
    }
    if (i < n) g_rowstart[i] = sm[threadIdx.x] - v;          // block-local exclusive
    if (threadIdx.x == SCB - 1) g_blksum[blockIdx.x] = sm[threadIdx.x];
}
__global__ void k_scan2(int nb) {
    __shared__ int sm[256];
    int v = (threadIdx.x < nb) ? g_blksum[threadIdx.x] : 0;
    sm[threadIdx.x] = v; __syncthreads();
    #pragma unroll
    for (int o = 1; o < 256; o <<= 1) {
        int t = (threadIdx.x >= o) ? sm[threadIdx.x - o] : 0;
        __syncthreads(); sm[threadIdx.x] += t; __syncthreads();
    }
    if (threadIdx.x < nb) g_blkoff[threadIdx.x] = sm[threadIdx.x] - v;
}
__global__ void k_scan3(int n, int E) {
    int i = blockIdx.x * blockDim.x + threadIdx.x;
    if (i < n) {
        int r = g_rowstart[i] + g_blkoff[i / SCB];
        g_rowstart[i] = r;
        g_cursor[i]   = r;
    }
    if (i == 0) g_rowstart[n] = E;
}
__global__ void k_fill(const int* __restrict__ src, const int* __restrict__ dst, int E) {
    int i = blockIdx.x * blockDim.x + threadIdx.x;
    if (i < E) {
        int pos = atomicAdd(&g_cursor[dst[i]], 1);
        g_esrc[pos] = src[i];
    }
}

// ---------------- tf32 mma ----------------
__device__ __forceinline__ void mma_tf32(float* c, uint32_t a0, uint32_t a1,
                                         uint32_t a2, uint32_t a3,
                                         uint32_t b0, uint32_t b1) {
    asm volatile(
        "mma.sync.aligned.m16n8k8.row.col.f32.tf32.tf32.f32 "
        "{%0,%1,%2,%3}, {%4,%5,%6,%7}, {%8,%9}, {%0,%1,%2,%3};"
        : "+f"(c[0]), "+f"(c[1]), "+f"(c[2]), "+f"(c[3])
        : "r"(a0), "r"(a1), "r"(a2), "r"(a3), "r"(b0), "r"(b1));
}

// ---- pipelined tf32 GEMM, inv-scale epilogue, single store ----
// LAYER==1: g_h1 = inv[row]*(Ain @ W1)   (N=128, K=512)
// LAYER==2: g_h2 = inv[row]*(g_acc1 @ W2) (N=64, K=128)
template<int BM, int BN, int BK, int LAYER>
__global__ __launch_bounds__(256)
void k_mma(const float* __restrict__ Ain, const float* __restrict__ Bw, int M, int K)
{
    constexpr int WARPS_N = BN / 64;
    constexpr int WARPS_M = 8 / WARPS_N;
    constexpr int WM      = BM / WARPS_M;
    constexpr int RT      = WM / 16;
    constexpr int ASTR    = BK + 4;          // 20: banks (4g+tg mod-pattern) conflict-free
    constexpr int BSTR    = BN + 8;          // stride mod 32 == 8 -> (8tg+g) conflict-free
    constexpr int A_CP    = BM*BK/4/256;     // cp.async per thread (A)
    constexpr int B_CP    = BK*BN/4/256;

    __shared__ float As[2][BM][ASTR];
    __shared__ float Bs[2][BK][BSTR];

    const float* A = (LAYER == 1) ? Ain : (const float*)g_acc1;
    float*       G = (LAYER == 1) ? (float*)g_h1 : (float*)g_h2;
    const int    N = BN;

    const int tid  = threadIdx.x;
    const int warp = tid >> 5;
    const int lane = tid & 31;
    const int g    = lane >> 2;
    const int tg   = lane & 3;
    const int wr   = (warp / WARPS_N) * WM;
    const int wc   = (warp % WARPS_N) * 64;
    const int rowBase = blockIdx.x * BM;

    float acc[RT][8][4] = {};

    auto load_tiles = [&](int st, int k0) {
        #pragma unroll
        for (int i = 0; i < A_CP; i++) {
            int id = tid + i*256;
            int m  = id / (BK/4), k4 = id % (BK/4);
            int row = rowBase + m;
            uint32_t da = (uint32_t)__cvta_generic_to_shared(&As[st][m][k4*4]);
            const float* sa = A + (size_t)row*K + k0 + k4*4;
            int sz = (row < M) ? 16 : 0;
            asm volatile("cp.async.cg.shared.global [%0],[%1],16,%2;"
                         :: "r"(da), "l"(sa), "r"(sz));
        }
        #pragma unroll
        for (int i = 0; i < B_CP; i++) {
            int id = tid + i*256;
            int kk = id / (BN/4), n4 = id % (BN/4);
            uint32_t db = (uint32_t)__cvta_generic_to_shared(&Bs[st][kk][n4*4]);
            const float* sb = Bw + (size_t)(k0+kk)*N + n4*4;
            asm volatile("cp.async.cg.shared.global [%0],[%1],16;"
                         :: "r"(db), "l"(sb));
        }
        asm volatile("cp.async.commit_group;");
    };

    const int KT = K / BK;
    load_tiles(0, 0);
    for (int kt = 0; kt < KT; kt++) {
        asm volatile("cp.async.wait_group 0;");
        __syncthreads();
        if (kt + 1 < KT) load_tiles((kt+1)&1, (kt+1)*BK);
        const int st = kt & 1;
        #pragma unroll
        for (int ks = 0; ks < BK/8; ks++) {
            int k = ks*8;
            uint32_t bf[8][2];
            #pragma unroll
            for (int j = 0; j < 8; j++) {
                bf[j][0] = __float_as_uint(Bs[st][k+tg  ][wc + j*8 + g]);
                bf[j][1] = __float_as_uint(Bs[st][k+tg+4][wc + j*8 + g]);
            }
            #pragma unroll
            for (int rt = 0; rt < RT; rt++) {
                int r = wr + rt*16;
                uint32_t a0 = __float_as_uint(As[st][r+g  ][k+tg  ]);
                uint32_t a1 = __float_as_uint(As[st][r+g+8][k+tg  ]);
                uint32_t a2 = __float_as_uint(As[st][r+g  ][k+tg+4]);
                uint32_t a3 = __float_as_uint(As[st][r+g+8][k+tg+4]);
                #pragma unroll
                for (int j = 0; j < 8; j++)
                    mma_tf32(acc[rt][j], a0, a1, a2, a3, bf[j][0], bf[j][1]);
            }
        }
        __syncthreads();
    }

    #pragma unroll
    for (int rt = 0; rt < RT; rt++) {
        int r0 = rowBase + wr + rt*16 + g;
        int r1 = r0 + 8;
        float s0 = (r0 < M) ? g_inv[r0] : 0.f;
        float s1 = (r1 < M) ? g_inv[r1] : 0.f;
        #pragma unroll
        for (int j = 0; j < 8; j++) {
            int col = wc + j*8 + tg*2;
            if (r0 < M) {
                float2 v; v.x = acc[rt][j][0]*s0; v.y = acc[rt][j][1]*s0;
                *(float2*)(G + (size_t)r0*N + col) = v;
            }
            if (r1 < M) {
                float2 v; v.x = acc[rt][j][2]*s1; v.y = acc[rt][j][3]*s1;
                *(float2*)(G + (size_t)r1*N + col) = v;
            }
        }
    }
}

// ---------------- gather layer 1: a1 = relu(inv*(g1[v] + sum g1[s]) + b1) ---
__global__ void k_gather1(const float* __restrict__ b1) {
    int w    = (blockIdx.x * blockDim.x + threadIdx.x) >> 5;
    int lane = threadIdx.x & 31;
    if (w >= N_NODES) return;
    const float* h = (const float*)g_h1;
    float4 acc = *(const float4*)(h + (size_t)w*HID + lane*4);   // self-loop term
    int i   = g_rowstart[w];
    int end = g_rowstart[w+1];
    for (; i + 1 < end; i += 2) {
        int s0 = g_esrc[i], s1 = g_esrc[i+1];
        float4 v0 = *(const float4*)(h + (size_t)s0*HID + lane*4);
        float4 v1 = *(const float4*)(h + (size_t)s1*HID + lane*4);
        acc.x += v0.x + v1.x; acc.y += v0.y + v1.y;
        acc.z += v0.z + v1.z; acc.w += v0.w + v1.w;
    }
    if (i < end) {
        int s = g_esrc[i];
        float4 v = *(const float4*)(h + (size_t)s*HID + lane*4);
        acc.x += v.x; acc.y += v.y; acc.z += v.z; acc.w += v.w;
    }
    float sc = g_inv[w];
    float4 bb = *(const float4*)(b1 + lane*4);
    float4 o;
    o.x = fmaxf(fmaf(sc, acc.x, bb.x), 0.f);
    o.y = fmaxf(fmaf(sc, acc.y, bb.y), 0.f);
    o.z = fmaxf(fmaf(sc, acc.z, bb.z), 0.f);
    o.w = fmaxf(fmaf(sc, acc.w, bb.w), 0.f);
    *(float4*)((float*)g_acc1 + (size_t)w*HID + lane*4) = o;
}

// ---------------- gather layer 2 + log_softmax -> out ----------------------
__global__ void k_gather2(float* __restrict__ out, const float* __restrict__ b2) {
    int w    = (blockIdx.x * blockDim.x + threadIdx.x) >> 5;
    int lane = threadIdx.x & 31;
    if (w >= N_NODES) return;
    const float* h = (const float*)g_h2;
    float2 acc = *(const float2*)(h + (size_t)w*CLS + lane*2);   // self-loop term
    int i   = g_rowstart[w];
    int end = g_rowstart[w+1];
    for (; i + 1 < end; i += 2) {
        int s0 = g_esrc[i], s1 = g_esrc[i+1];
        float2 v0 = *(const float2*)(h + (size_t)s0*CLS + lane*2);
        float2 v1 = *(const float2*)(h + (size_t)s1*CLS + lane*2);
        acc.x += v0.x + v1.x; acc.y += v0.y + v1.y;
    }
    if (i < end) {
        int s = g_esrc[i];
        float2 v = *(const float2*)(h + (size_t)s*CLS + lane*2);
        acc.x += v.x; acc.y += v.y;
    }
    float sc = g_inv[w];
    float t0 = fmaf(sc, acc.x, b2[lane*2+0]);
    float t1 = fmaf(sc, acc.y, b2[lane*2+1]);
    float m = fmaxf(t0, t1);
    #pragma unroll
    for (int o = 16; o > 0; o >>= 1) m = fmaxf(m, __shfl_xor_sync(0xffffffffu, m, o));
    float sum = __expf(t0 - m) + __expf(t1 - m);
    #pragma unroll
    for (int o = 16; o > 0; o >>= 1) sum += __shfl_xor_sync(0xffffffffu, sum, o);
    float ls = m + __logf(sum);
    float2 r; r.x = t0 - ls; r.y = t1 - ls;
    *(float2*)(out + (size_t)w*CLS + lane*2) = r;
}

// ---------------- launch ----------------
extern "C" void kernel_launch(void* const* d_in, const int* in_sizes, int n_in,
                              void* d_out, int out_size)
{
    const float* x   = (const float*)d_in[0];
    const int*   src = (const int*)d_in[1];     // int32 (JAX x64 disabled)
    const int*   dst = (const int*)d_in[2];
    const float* W1  = (const float*)d_in[3];
    const float* b1  = (const float*)d_in[4];
    const float* W2  = (const float*)d_in[5];
    const float* b2  = (const float*)d_in[6];
    float* out = (float*)d_out;
    const int E = in_sizes[1];

    const int nb256 = (N_NODES + 255)/256;
    const int eb256 = (E + 255)/256;
    const int sb    = (N_NODES + SCB - 1)/SCB;     // 196
    const int gx    = (N_NODES + 127)/128;          // 782
    const int gwarp = (N_NODES*32 + 255)/256;       // 12500

    // CSR-by-dst build + normalization
    k_zero <<<nb256, 256>>>();
    k_hist <<<eb256, 256>>>(dst, E);
    k_inv  <<<nb256, 256>>>();
    k_scan1<<<sb, SCB>>>(N_NODES);
    k_scan2<<<1, 256>>>(sb);
    k_scan3<<<sb, SCB>>>(N_NODES, E);
    k_fill <<<eb256, 256>>>(src, dst, E);

    // layer 1
    k_mma<128,128,16,1><<<gx, 256>>>(x, W1, N_NODES, F_IN);
    k_gather1<<<gwarp, 256>>>(b1);

    // layer 2
    k_mma<128,64,16,2><<<gx, 256>>>(nullptr, W2, N_NODES, HID);
    k_gather2<<<gwarp, 256>>>(out, b2);
}

// round 7
// speedup vs baseline: 3.9916x; 1.1011x over previous
#include <cuda_runtime.h>
#include <cuda_fp16.h>
#include <math.h>
#include <stdint.h>

#define N_NODES 100000
#define F_IN    512
#define HID     128
#define CLS     64
#define E_MAX   1600000

// ---------------- scratch (no cudaMalloc allowed) ----------------
__device__ __half g_h1h[(size_t)N_NODES * HID];  // g1 = inv*(x@W1), fp16
__device__ float  g_acc1[(size_t)N_NODES * HID]; // a1 = relu(inv*sum + b1), fp32
__device__ __half g_h2h[(size_t)N_NODES * CLS];  // g2 = inv*(a1@W2), fp16
__device__ float  g_inv [N_NODES];
__device__ int    g_cnt [N_NODES];
__device__ int    g_rowstart[N_NODES + 1];
__device__ int    g_cursor[N_NODES];
__device__ int    g_blksum[256];
__device__ int    g_blkoff[256];
__device__ int    g_esrc[E_MAX];

// ---------------- degree histogram + inv sqrt ----------------
__global__ void k_zero() {
    int i = blockIdx.x * blockDim.x + threadIdx.x;
    if (i < N_NODES) g_cnt[i] = 0;
}
__global__ void k_hist(const int* __restrict__ dst, int E) {
    int i = blockIdx.x * blockDim.x + threadIdx.x;
    if (i < E) atomicAdd(&g_cnt[dst[i]], 1);
}
__global__ void k_inv() {
    int i = blockIdx.x * blockDim.x + threadIdx.x;
    if (i < N_NODES) g_inv[i] = rsqrtf((float)(1 + g_cnt[i]));  // +1 self-loop
}

// ---------------- exclusive scan over g_cnt (3 kernels) ----------------
#define SCB 512
__global__ void k_scan1(int n) {
    __shared__ int sm[SCB];
    int i = blockIdx.x * SCB + threadIdx.x;
    int v = (i < n) ? g_cnt[i] : 0;
    sm[threadIdx.x] = v; __syncthreads();
    #pragma unroll
    for (int o = 1; o < SCB; o <<= 1) {
        int t = (threadIdx.x >= o) ? sm[threadIdx.x - o] : 0;
        __syncthreads(); sm[threadIdx.x] += t; __syncthreads();
    }
    if (i < n) g_rowstart[i] = sm[threadIdx.x] - v;
    if (threadIdx.x == SCB - 1) g_blksum[blockIdx.x] = sm[threadIdx.x];
}
__global__ void k_scan2(int nb) {
    __shared__ int sm[256];
    int v = (threadIdx.x < nb) ? g_blksum[threadIdx.x] : 0;
    sm[threadIdx.x] = v; __syncthreads();
    #pragma unroll
    for (int o = 1; o < 256; o <<= 1) {
        int t = (threadIdx.x >= o) ? sm[threadIdx.x - o] : 0;
        __syncthreads(); sm[threadIdx.x] += t; __syncthreads();
    }
    if (threadIdx.x < nb) g_blkoff[threadIdx.x] = sm[threadIdx.x] - v;
}
__global__ void k_scan3(int n, int E) {
    int i = blockIdx.x * blockDim.x + threadIdx.x;
    if (i < n) {
        int r = g_rowstart[i] + g_blkoff[i / SCB];
        g_rowstart[i] = r;
        g_cursor[i]   = r;
    }
    if (i == 0) g_rowstart[n] = E;
}
__global__ void k_fill(const int* __restrict__ src, const int* __restrict__ dst, int E) {
    int i = blockIdx.x * blockDim.x + threadIdx.x;
    if (i < E) {
        int pos = atomicAdd(&g_cursor[dst[i]], 1);
        g_esrc[pos] = src[i];
    }
}

// ---------------- tf32 mma ----------------
__device__ __forceinline__ void mma_tf32(float* c, uint32_t a0, uint32_t a1,
                                         uint32_t a2, uint32_t a3,
                                         uint32_t b0, uint32_t b1) {
    asm volatile(
        "mma.sync.aligned.m16n8k8.row.col.f32.tf32.tf32.f32 "
        "{%0,%1,%2,%3}, {%4,%5,%6,%7}, {%8,%9}, {%0,%1,%2,%3};"
        : "+f"(c[0]), "+f"(c[1]), "+f"(c[2]), "+f"(c[3])
        : "r"(a0), "r"(a1), "r"(a2), "r"(a3), "r"(b0), "r"(b1));
}

// ---- pipelined tf32 GEMM, inv-scale epilogue, fp16 store ----
// LAYER==1: g_h1h = fp16( inv[row]*(Ain @ W1) )    (N=128, K=512)
// LAYER==2: g_h2h = fp16( inv[row]*(g_acc1 @ W2) ) (N=64,  K=128)
template<int BM, int BN, int BK, int LAYER>
__global__ __launch_bounds__(256)
void k_mma(const float* __restrict__ Ain, const float* __restrict__ Bw, int M, int K)
{
    constexpr int WARPS_N = BN / 64;
    constexpr int WARPS_M = 8 / WARPS_N;
    constexpr int WM      = BM / WARPS_M;
    constexpr int RT      = WM / 16;
    constexpr int ASTR    = BK + 4;
    constexpr int BSTR    = BN + 8;
    constexpr int A_CP    = BM*BK/4/256;
    constexpr int B_CP    = BK*BN/4/256;

    __shared__ float As[2][BM][ASTR];
    __shared__ float Bs[2][BK][BSTR];

    const float* A = (LAYER == 1) ? Ain : (const float*)g_acc1;
    __half*      G = (LAYER == 1) ? (__half*)g_h1h : (__half*)g_h2h;
    const int    N = BN;

    const int tid  = threadIdx.x;
    const int warp = tid >> 5;
    const int lane = tid & 31;
    const int g    = lane >> 2;
    const int tg   = lane & 3;
    const int wr   = (warp / WARPS_N) * WM;
    const int wc   = (warp % WARPS_N) * 64;
    const int rowBase = blockIdx.x * BM;

    float acc[RT][8][4] = {};

    auto load_tiles = [&](int st, int k0) {
        #pragma unroll
        for (int i = 0; i < A_CP; i++) {
            int id = tid + i*256;
            int m  = id / (BK/4), k4 = id % (BK/4);
            int row = rowBase + m;
            uint32_t da = (uint32_t)__cvta_generic_to_shared(&As[st][m][k4*4]);
            const float* sa = A + (size_t)row*K + k0 + k4*4;
            int sz = (row < M) ? 16 : 0;
            asm volatile("cp.async.cg.shared.global [%0],[%1],16,%2;"
                         :: "r"(da), "l"(sa), "r"(sz));
        }
        #pragma unroll
        for (int i = 0; i < B_CP; i++) {
            int id = tid + i*256;
            int kk = id / (BN/4), n4 = id % (BN/4);
            uint32_t db = (uint32_t)__cvta_generic_to_shared(&Bs[st][kk][n4*4]);
            const float* sb = Bw + (size_t)(k0+kk)*N + n4*4;
            asm volatile("cp.async.cg.shared.global [%0],[%1],16;"
                         :: "r"(db), "l"(sb));
        }
        asm volatile("cp.async.commit_group;");
    };

    const int KT = K / BK;
    load_tiles(0, 0);
    for (int kt = 0; kt < KT; kt++) {
        asm volatile("cp.async.wait_group 0;");
        __syncthreads();
        if (kt + 1 < KT) load_tiles((kt+1)&1, (kt+1)*BK);
        const int st = kt & 1;
        #pragma unroll
        for (int ks = 0; ks < BK/8; ks++) {
            int k = ks*8;
            uint32_t bf[8][2];
            #pragma unroll
            for (int j = 0; j < 8; j++) {
                bf[j][0] = __float_as_uint(Bs[st][k+tg  ][wc + j*8 + g]);
                bf[j][1] = __float_as_uint(Bs[st][k+tg+4][wc + j*8 + g]);
            }
            #pragma unroll
            for (int rt = 0; rt < RT; rt++) {
                int r = wr + rt*16;
                uint32_t a0 = __float_as_uint(As[st][r+g  ][k+tg  ]);
                uint32_t a1 = __float_as_uint(As[st][r+g+8][k+tg  ]);
                uint32_t a2 = __float_as_uint(As[st][r+g  ][k+tg+4]);
                uint32_t a3 = __float_as_uint(As[st][r+g+8][k+tg+4]);
                #pragma unroll
                for (int j = 0; j < 8; j++)
                    mma_tf32(acc[rt][j], a0, a1, a2, a3, bf[j][0], bf[j][1]);
            }
        }
        __syncthreads();
    }

    #pragma unroll
    for (int rt = 0; rt < RT; rt++) {
        int r0 = rowBase + wr + rt*16 + g;
        int r1 = r0 + 8;
        float s0 = (r0 < M) ? g_inv[r0] : 0.f;
        float s1 = (r1 < M) ? g_inv[r1] : 0.f;
        #pragma unroll
        for (int j = 0; j < 8; j++) {
            int col = wc + j*8 + tg*2;
            if (r0 < M) {
                __half2 v = __floats2half2_rn(acc[rt][j][0]*s0, acc[rt][j][1]*s0);
                *(__half2*)(G + (size_t)r0*N + col) = v;
            }
            if (r1 < M) {
                __half2 v = __floats2half2_rn(acc[rt][j][2]*s1, acc[rt][j][3]*s1);
                *(__half2*)(G + (size_t)r1*N + col) = v;
            }
        }
    }
}

// ---------------- fp16 load helpers ----------------
__device__ __forceinline__ float4 ld_h4(const __half* p) {
    uint2 u = *(const uint2*)p;
    float2 a = __half22float2(*(__half2*)&u.x);
    float2 b = __half22float2(*(__half2*)&u.y);
    return make_float4(a.x, a.y, b.x, b.y);
}
__device__ __forceinline__ float2 ld_h2(const __half* p) {
    uint32_t u = *(const uint32_t*)p;
    return __half22float2(*(__half2*)&u);
}

// ---------------- gather layer 1: a1 = relu(inv*(g1[v] + sum g1[s]) + b1) ---
__global__ void k_gather1(const float* __restrict__ b1) {
    int w    = (blockIdx.x * blockDim.x + threadIdx.x) >> 5;
    int lane = threadIdx.x & 31;
    if (w >= N_NODES) return;
    const __half* h = (const __half*)g_h1h;
    float4 acc = ld_h4(h + (size_t)w*HID + lane*4);          // self-loop term
    int i   = g_rowstart[w];
    int end = g_rowstart[w+1];
    for (; i + 3 < end; i += 4) {
        int s0 = g_esrc[i],   s1 = g_esrc[i+1];
        int s2 = g_esrc[i+2], s3 = g_esrc[i+3];
        float4 v0 = ld_h4(h + (size_t)s0*HID + lane*4);
        float4 v1 = ld_h4(h + (size_t)s1*HID + lane*4);
        float4 v2 = ld_h4(h + (size_t)s2*HID + lane*4);
        float4 v3 = ld_h4(h + (size_t)s3*HID + lane*4);
        acc.x += (v0.x + v1.x) + (v2.x + v3.x);
        acc.y += (v0.y + v1.y) + (v2.y + v3.y);
        acc.z += (v0.z + v1.z) + (v2.z + v3.z);
        acc.w += (v0.w + v1.w) + (v2.w + v3.w);
    }
    for (; i < end; i++) {
        int s = g_esrc[i];
        float4 v = ld_h4(h + (size_t)s*HID + lane*4);
        acc.x += v.x; acc.y += v.y; acc.z += v.z; acc.w += v.w;
    }
    float sc = g_inv[w];
    float4 bb = *(const float4*)(b1 + lane*4);
    float4 o;
    o.x = fmaxf(fmaf(sc, acc.x, bb.x), 0.f);
    o.y = fmaxf(fmaf(sc, acc.y, bb.y), 0.f);
    o.z = fmaxf(fmaf(sc, acc.z, bb.z), 0.f);
    o.w = fmaxf(fmaf(sc, acc.w, bb.w), 0.f);
    *(float4*)((float*)g_acc1 + (size_t)w*HID + lane*4) = o;
}

// ---------------- gather layer 2 + log_softmax -> out ----------------------
__global__ void k_gather2(float* __restrict__ out, const float* __restrict__ b2) {
    int w    = (blockIdx.x * blockDim.x + threadIdx.x) >> 5;
    int lane = threadIdx.x & 31;
    if (w >= N_NODES) return;
    const __half* h = (const __half*)g_h2h;
    float2 acc = ld_h2(h + (size_t)w*CLS + lane*2);          // self-loop term
    int i   = g_rowstart[w];
    int end = g_rowstart[w+1];
    for (; i + 3 < end; i += 4) {
        int s0 = g_esrc[i],   s1 = g_esrc[i+1];
        int s2 = g_esrc[i+2], s3 = g_esrc[i+3];
        float2 v0 = ld_h2(h + (size_t)s0*CLS + lane*2);
        float2 v1 = ld_h2(h + (size_t)s1*CLS + lane*2);
        float2 v2 = ld_h2(h + (size_t)s2*CLS + lane*2);
        float2 v3 = ld_h2(h + (size_t)s3*CLS + lane*2);
        acc.x += (v0.x + v1.x) + (v2.x + v3.x);
        acc.y += (v0.y + v1.y) + (v2.y + v3.y);
    }
    for (; i < end; i++) {
        int s = g_esrc[i];
        float2 v = ld_h2(h + (size_t)s*CLS + lane*2);
        acc.x += v.x; acc.y += v.y;
    }
    float sc = g_inv[w];
    float t0 = fmaf(sc, acc.x, b2[lane*2+0]);
    float t1 = fmaf(sc, acc.y, b2[lane*2+1]);
    float m = fmaxf(t0, t1);
    #pragma unroll
    for (int o = 16; o > 0; o >>= 1) m = fmaxf(m, __shfl_xor_sync(0xffffffffu, m, o));
    float sum = __expf(t0 - m) + __expf(t1 - m);
    #pragma unroll
    for (int o = 16; o > 0; o >>= 1) sum += __shfl_xor_sync(0xffffffffu, sum, o);
    float ls = m + __logf(sum);
    float2 r; r.x = t0 - ls; r.y = t1 - ls;
    *(float2*)(out + (size_t)w*CLS + lane*2) = r;
}

// ---------------- launch ----------------
extern "C" void kernel_launch(void* const* d_in, const int* in_sizes, int n_in,
                              void* d_out, int out_size)
{
    const float* x   = (const float*)d_in[0];
    const int*   src = (const int*)d_in[1];     // int32 (JAX x64 disabled)
    const int*   dst = (const int*)d_in[2];
    const float* W1  = (const float*)d_in[3];
    const float* b1  = (const float*)d_in[4];
    const float* W2  = (const float*)d_in[5];
    const float* b2  = (const float*)d_in[6];
    float* out = (float*)d_out;
    const int E = in_sizes[1];

    const int nb256 = (N_NODES + 255)/256;
    const int eb256 = (E + 255)/256;
    const int sb    = (N_NODES + SCB - 1)/SCB;
    const int gx    = (N_NODES + 127)/128;
    const int gwarp = (N_NODES*32 + 255)/256;

    // CSR-by-dst build + normalization
    k_zero <<<nb256, 256>>>();
    k_hist <<<eb256, 256>>>(dst, E);
    k_inv  <<<nb256, 256>>>();
    k_scan1<<<sb, SCB>>>(N_NODES);
    k_scan2<<<1, 256>>>(sb);
    k_scan3<<<sb, SCB>>>(N_NODES, E);
    k_fill <<<eb256, 256>>>(src, dst, E);

    // layer 1
    k_mma<128,128,16,1><<<gx, 256>>>(x, W1, N_NODES, F_IN);
    k_gather1<<<gwarp, 256>>>(b1);

    // layer 2
    k_mma<128,64,16,2><<<gx, 256>>>(nullptr, W2, N_NODES, HID);
    k_gather2<<<gwarp, 256>>>(out, b2);
}

// round 8
// speedup vs baseline: 4.0582x; 1.0167x over previous
#include <cuda_runtime.h>
#include <cuda_fp16.h>
#include <math.h>
#include <stdint.h>

#define N_NODES 100000
#define F_IN    512
#define HID     128
#define CLS     64
#define E_MAX   1600000

// ---------------- scratch (no cudaMalloc allowed) ----------------
__device__ __half g_h1h[(size_t)N_NODES * HID];  // g1 = inv*(x@W1), fp16
__device__ float  g_acc1[(size_t)N_NODES * HID]; // a1 = relu(inv*sum + b1), fp32
__device__ __half g_h2h[(size_t)N_NODES * CLS];  // g2 = inv*(a1@W2), fp16
__device__ float  g_inv [N_NODES];
__device__ int    g_cnt [N_NODES];
__device__ int    g_rowstart[N_NODES + 1];
__device__ int    g_cursor[N_NODES];
__device__ int    g_blksum[256];
__device__ int    g_blkoff[256];
__device__ int    g_esrc[E_MAX];

// ---------------- degree histogram + inv sqrt ----------------
__global__ void k_zero() {
    int i = blockIdx.x * blockDim.x + threadIdx.x;
    if (i < N_NODES) g_cnt[i] = 0;
}
__global__ void k_hist(const int* __restrict__ dst, int E) {
    int i = blockIdx.x * blockDim.x + threadIdx.x;
    if (i < E) atomicAdd(&g_cnt[dst[i]], 1);
}
__global__ void k_inv() {
    int i = blockIdx.x * blockDim.x + threadIdx.x;
    if (i < N_NODES) g_inv[i] = rsqrtf((float)(1 + g_cnt[i]));  // +1 self-loop
}

// ---------------- exclusive scan over g_cnt (3 kernels) ----------------
#define SCB 512
__global__ void k_scan1(int n) {
    __shared__ int sm[SCB];
    int i = blockIdx.x * SCB + threadIdx.x;
    int v = (i < n) ? g_cnt[i] : 0;
    sm[threadIdx.x] = v; __syncthreads();
    #pragma unroll
    for (int o = 1; o < SCB; o <<= 1) {
        int t = (threadIdx.x >= o) ? sm[threadIdx.x - o] : 0;
        __syncthreads(); sm[threadIdx.x] += t; __syncthreads();
    }
    if (i < n) g_rowstart[i] = sm[threadIdx.x] - v;
    if (threadIdx.x == SCB - 1) g_blksum[blockIdx.x] = sm[threadIdx.x];
}
__global__ void k_scan2(int nb) {
    __shared__ int sm[256];
    int v = (threadIdx.x < nb) ? g_blksum[threadIdx.x] : 0;
    sm[threadIdx.x] = v; __syncthreads();
    #pragma unroll
    for (int o = 1; o < 256; o <<= 1) {
        int t = (threadIdx.x >= o) ? sm[threadIdx.x - o] : 0;
        __syncthreads(); sm[threadIdx.x] += t; __syncthreads();
    }
    if (threadIdx.x < nb) g_blkoff[threadIdx.x] = sm[threadIdx.x] - v;
}
__global__ void k_scan3(int n, int E) {
    int i = blockIdx.x * blockDim.x + threadIdx.x;
    if (i < n) {
        int r = g_rowstart[i] + g_blkoff[i / SCB];
        g_rowstart[i] = r;
        g_cursor[i]   = r;
    }
    if (i == 0) g_rowstart[n] = E;
}
__global__ void k_fill(const int* __restrict__ src, const int* __restrict__ dst, int E) {
    int i = blockIdx.x * blockDim.x + threadIdx.x;
    if (i < E) {
        int pos = atomicAdd(&g_cursor[dst[i]], 1);
        g_esrc[pos] = src[i];
    }
}

// ---------------- tf32 mma ----------------
__device__ __forceinline__ void mma_tf32(float* c, uint32_t a0, uint32_t a1,
                                         uint32_t a2, uint32_t a3,
                                         uint32_t b0, uint32_t b1) {
    asm volatile(
        "mma.sync.aligned.m16n8k8.row.col.f32.tf32.tf32.f32 "
        "{%0,%1,%2,%3}, {%4,%5,%6,%7}, {%8,%9}, {%0,%1,%2,%3};"
        : "+f"(c[0]), "+f"(c[1]), "+f"(c[2]), "+f"(c[3])
        : "r"(a0), "r"(a1), "r"(a2), "r"(a3), "r"(b0), "r"(b1));
}

// ---- 3-stage pipelined tf32 GEMM, inv-scale epilogue, fp16 store ----
// LAYER==1: g_h1h = fp16( inv[row]*(Ain @ W1) )    (N=128, K=512)
// LAYER==2: g_h2h = fp16( inv[row]*(g_acc1 @ W2) ) (N=64,  K=128)
template<int BM, int BN, int BK, int LAYER>
__global__ __launch_bounds__(256)
void k_mma(const float* __restrict__ Ain, const float* __restrict__ Bw, int M, int K)
{
    constexpr int WARPS_N = BN / 64;
    constexpr int WARPS_M = 8 / WARPS_N;
    constexpr int WM      = BM / WARPS_M;
    constexpr int RT      = WM / 16;
    constexpr int ASTR    = BK + 4;
    constexpr int BSTR    = BN + 8;
    constexpr int A_CP    = BM*BK/4/256;
    constexpr int B_CP    = BK*BN/4/256;
    constexpr int STAGES  = 3;

    __shared__ float As[STAGES][BM][ASTR];
    __shared__ float Bs[STAGES][BK][BSTR];

    const float* A = (LAYER == 1) ? Ain : (const float*)g_acc1;
    __half*      G = (LAYER == 1) ? (__half*)g_h1h : (__half*)g_h2h;
    const int    N = BN;

    const int tid  = threadIdx.x;
    const int warp = tid >> 5;
    const int lane = tid & 31;
    const int g    = lane >> 2;
    const int tg   = lane & 3;
    const int wr   = (warp / WARPS_N) * WM;
    const int wc   = (warp % WARPS_N) * 64;
    const int rowBase = blockIdx.x * BM;

    float acc[RT][8][4] = {};

    auto load_tiles = [&](int st, int k0) {
        #pragma unroll
        for (int i = 0; i < A_CP; i++) {
            int id = tid + i*256;
            int m  = id / (BK/4), k4 = id % (BK/4);
            int row = rowBase + m;
            uint32_t da = (uint32_t)__cvta_generic_to_shared(&As[st][m][k4*4]);
            const float* sa = A + (size_t)row*K + k0 + k4*4;
            int sz = (row < M) ? 16 : 0;
            asm volatile("cp.async.cg.shared.global [%0],[%1],16,%2;"
                         :: "r"(da), "l"(sa), "r"(sz));
        }
        #pragma unroll
        for (int i = 0; i < B_CP; i++) {
            int id = tid + i*256;
            int kk = id / (BN/4), n4 = id % (BN/4);
            uint32_t db = (uint32_t)__cvta_generic_to_shared(&Bs[st][kk][n4*4]);
            const float* sb = Bw + (size_t)(k0+kk)*N + n4*4;
            asm volatile("cp.async.cg.shared.global [%0],[%1],16;"
                         :: "r"(db), "l"(sb));
        }
        asm volatile("cp.async.commit_group;");
    };

    const int KT = K / BK;           // 32 (L1) / 8 (L2), both >= 2
    load_tiles(0, 0);
    load_tiles(1, BK);
    int st = 0;
    for (int kt = 0; kt < KT; kt++) {
        asm volatile("cp.async.wait_group 1;");   // stage kt resident; kt+1 may be in flight
        __syncthreads();
        if (kt + 2 < KT) {
            int nst = st + 2; if (nst >= STAGES) nst -= STAGES;
            load_tiles(nst, (kt+2)*BK);
        }
        #pragma unroll
        for (int ks = 0; ks < BK/8; ks++) {
            int k = ks*8;
            uint32_t bf[8][2];
            #pragma unroll
            for (int j = 0; j < 8; j++) {
                bf[j][0] = __float_as_uint(Bs[st][k+tg  ][wc + j*8 + g]);
                bf[j][1] = __float_as_uint(Bs[st][k+tg+4][wc + j*8 + g]);
            }
            #pragma unroll
            for (int rt = 0; rt < RT; rt++) {
                int r = wr + rt*16;
                uint32_t a0 = __float_as_uint(As[st][r+g  ][k+tg  ]);
                uint32_t a1 = __float_as_uint(As[st][r+g+8][k+tg  ]);
                uint32_t a2 = __float_as_uint(As[st][r+g  ][k+tg+4]);
                uint32_t a3 = __float_as_uint(As[st][r+g+8][k+tg+4]);
                #pragma unroll
                for (int j = 0; j < 8; j++)
                    mma_tf32(acc[rt][j], a0, a1, a2, a3, bf[j][0], bf[j][1]);
            }
        }
        if (++st >= STAGES) st = 0;
    }

    #pragma unroll
    for (int rt = 0; rt < RT; rt++) {
        int r0 = rowBase + wr + rt*16 + g;
        int r1 = r0 + 8;
        float s0 = (r0 < M) ? g_inv[r0] : 0.f;
        float s1 = (r1 < M) ? g_inv[r1] : 0.f;
        #pragma unroll
        for (int j = 0; j < 8; j++) {
            int col = wc + j*8 + tg*2;
            if (r0 < M) {
                __half2 v = __floats2half2_rn(acc[rt][j][0]*s0, acc[rt][j][1]*s0);
                *(__half2*)(G + (size_t)r0*N + col) = v;
            }
            if (r1 < M) {
                __half2 v = __floats2half2_rn(acc[rt][j][2]*s1, acc[rt][j][3]*s1);
                *(__half2*)(G + (size_t)r1*N + col) = v;
            }
        }
    }
}

// ---------------- fp16 load helpers ----------------
__device__ __forceinline__ float4 ld_h4(const __half* p) {
    uint2 u = *(const uint2*)p;
    float2 a = __half22float2(*(__half2*)&u.x);
    float2 b = __half22float2(*(__half2*)&u.y);
    return make_float4(a.x, a.y, b.x, b.y);
}
__device__ __forceinline__ float2 ld_h2(const __half* p) {
    uint32_t u = *(const uint32_t*)p;
    return __half22float2(*(__half2*)&u);
}

// ---------------- gather layer 1: a1 = relu(inv*(g1[v] + sum g1[s]) + b1) ---
__global__ void k_gather1(const float* __restrict__ b1) {
    int w    = (blockIdx.x * blockDim.x + threadIdx.x) >> 5;
    int lane = threadIdx.x & 31;
    if (w >= N_NODES) return;
    const __half* h = (const __half*)g_h1h;
    float4 acc = ld_h4(h + (size_t)w*HID + lane*4);          // self-loop term
    int i   = g_rowstart[w];
    int end = g_rowstart[w+1];
    for (; i + 3 < end; i += 4) {
        int s0 = g_esrc[i],   s1 = g_esrc[i+1];
        int s2 = g_esrc[i+2], s3 = g_esrc[i+3];
        float4 v0 = ld_h4(h + (size_t)s0*HID + lane*4);
        float4 v1 = ld_h4(h + (size_t)s1*HID + lane*4);
        float4 v2 = ld_h4(h + (size_t)s2*HID + lane*4);
        float4 v3 = ld_h4(h + (size_t)s3*HID + lane*4);
        acc.x += (v0.x + v1.x) + (v2.x + v3.x);
        acc.y += (v0.y + v1.y) + (v2.y + v3.y);
        acc.z += (v0.z + v1.z) + (v2.z + v3.z);
        acc.w += (v0.w + v1.w) + (v2.w + v3.w);
    }
    for (; i < end; i++) {
        int s = g_esrc[i];
        float4 v = ld_h4(h + (size_t)s*HID + lane*4);
        acc.x += v.x; acc.y += v.y; acc.z += v.z; acc.w += v.w;
    }
    float sc = g_inv[w];
    float4 bb = *(const float4*)(b1 + lane*4);
    float4 o;
    o.x = fmaxf(fmaf(sc, acc.x, bb.x), 0.f);
    o.y = fmaxf(fmaf(sc, acc.y, bb.y), 0.f);
    o.z = fmaxf(fmaf(sc, acc.z, bb.z), 0.f);
    o.w = fmaxf(fmaf(sc, acc.w, bb.w), 0.f);
    *(float4*)((float*)g_acc1 + (size_t)w*HID + lane*4) = o;
}

// ---------------- gather layer 2 + log_softmax -> out ----------------------
__global__ void k_gather2(float* __restrict__ out, const float* __restrict__ b2) {
    int w    = (blockIdx.x * blockDim.x + threadIdx.x) >> 5;
    int lane = threadIdx.x & 31;
    if (w >= N_NODES) return;
    const __half* h = (const __half*)g_h2h;
    float2 acc = ld_h2(h + (size_t)w*CLS + lane*2);          // self-loop term
    int i   = g_rowstart[w];
    int end = g_rowstart[w+1];
    for (; i + 3 < end; i += 4) {
        int s0 = g_esrc[i],   s1 = g_esrc[i+1];
        int s2 = g_esrc[i+2], s3 = g_esrc[i+3];
        float2 v0 = ld_h2(h + (size_t)s0*CLS + lane*2);
        float2 v1 = ld_h2(h + (size_t)s1*CLS + lane*2);
        float2 v2 = ld_h2(h + (size_t)s2*CLS + lane*2);
        float2 v3 = ld_h2(h + (size_t)s3*CLS + lane*2);
        acc.x += (v0.x + v1.x) + (v2.x + v3.x);
        acc.y += (v0.y + v1.y) + (v2.y + v3.y);
    }
    for (; i < end; i++) {
        int s = g_esrc[i];
        float2 v = ld_h2(h + (size_t)s*CLS + lane*2);
        acc.x += v.x; acc.y += v.y;
    }
    float sc = g_inv[w];
    float t0 = fmaf(sc, acc.x, b2[lane*2+0]);
    float t1 = fmaf(sc, acc.y, b2[lane*2+1]);
    float m = fmaxf(t0, t1);
    #pragma unroll
    for (int o = 16; o > 0; o >>= 1) m = fmaxf(m, __shfl_xor_sync(0xffffffffu, m, o));
    float sum = __expf(t0 - m) + __expf(t1 - m);
    #pragma unroll
    for (int o = 16; o > 0; o >>= 1) sum += __shfl_xor_sync(0xffffffffu, sum, o);
    float ls = m + __logf(sum);
    float2 r; r.x = t0 - ls; r.y = t1 - ls;
    *(float2*)(out + (size_t)w*CLS + lane*2) = r;
}

// ---------------- launch ----------------
extern "C" void kernel_launch(void* const* d_in, const int* in_sizes, int n_in,
                              void* d_out, int out_size)
{
    const float* x   = (const float*)d_in[0];
    const int*   src = (const int*)d_in[1];     // int32 (JAX x64 disabled)
    const int*   dst = (const int*)d_in[2];
    const float* W1  = (const float*)d_in[3];
    const float* b1  = (const float*)d_in[4];
    const float* W2  = (const float*)d_in[5];
    const float* b2  = (const float*)d_in[6];
    float* out = (float*)d_out;
    const int E = in_sizes[1];

    const int nb256 = (N_NODES + 255)/256;
    const int eb256 = (E + 255)/256;
    const int sb    = (N_NODES + SCB - 1)/SCB;
    const int gx    = (N_NODES + 127)/128;
    const int gwarp = (N_NODES*32 + 255)/256;

    // CSR-by-dst build + normalization
    k_zero <<<nb256, 256>>>();
    k_hist <<<eb256, 256>>>(dst, E);
    k_inv  <<<nb256, 256>>>();
    k_scan1<<<sb, SCB>>>(N_NODES);
    k_scan2<<<1, 256>>>(sb);
    k_scan3<<<sb, SCB>>>(N_NODES, E);
    k_fill <<<eb256, 256>>>(src, dst, E);

    // layer 1
    k_mma<128,128,16,1><<<gx, 256>>>(x, W1, N_NODES, F_IN);
    k_gather1<<<gwarp, 256>>>(b1);

    // layer 2
    k_mma<128,64,16,2><<<gx, 256>>>(nullptr, W2, N_NODES, HID);
    k_gather2<<<gwarp, 256>>>(out, b2);
}

// round 9
// speedup vs baseline: 4.8275x; 1.1896x over previous
#include <cuda_runtime.h>
#include <cuda_fp16.h>
#include <math.h>
#include <stdint.h>

#define N_NODES 100000
#define F_IN    512
#define HID     128
#define CLS     64
#define E_MAX   1600000

// ---------------- scratch (no cudaMalloc allowed) ----------------
__device__ __half g_h1h[(size_t)N_NODES * HID];  // g1 = inv*(x@W1), fp16
__device__ float  g_acc1[(size_t)N_NODES * HID]; // a1 = relu(inv*sum + b1), fp32
__device__ __half g_h2h[(size_t)N_NODES * CLS];  // g2 = inv*(a1@W2), fp16
__device__ __half g_W1t[(size_t)HID * F_IN];     // W1 transposed, n-major, fp16
__device__ __half g_W2t[(size_t)CLS * HID];      // W2 transposed, n-major, fp16
__device__ float  g_inv [N_NODES];
__device__ int    g_cnt [N_NODES];
__device__ int    g_rowstart[N_NODES + 1];
__device__ int    g_cursor[N_NODES];
__device__ int    g_blksum[256];
__device__ int    g_blkoff[256];
__device__ int    g_esrc[E_MAX];

// ---------------- weight transpose + fp16 convert (one-time, tiny) --------
__global__ void k_prepw(const float* __restrict__ W1, const float* __restrict__ W2) {
    int i = blockIdx.x * blockDim.x + threadIdx.x;
    if (i < HID * F_IN) {
        int n = i / F_IN, k = i % F_IN;
        g_W1t[i] = __float2half(W1[(size_t)k * HID + n]);
    }
    if (i < CLS * HID) {
        int n = i / HID, k = i % HID;
        g_W2t[i] = __float2half(W2[(size_t)k * CLS + n]);
    }
}

// ---------------- degree histogram ----------------
__global__ void k_zero() {
    int i = blockIdx.x * blockDim.x + threadIdx.x;
    if (i < N_NODES) g_cnt[i] = 0;
}
__global__ void k_hist(const int* __restrict__ dst, int E) {
    int i = blockIdx.x * blockDim.x + threadIdx.x;
    if (i < E) atomicAdd(&g_cnt[dst[i]], 1);
}

// ---------------- exclusive scan over g_cnt (3 kernels) ----------------
#define SCB 512
__global__ void k_scan1(int n) {
    __shared__ int sm[SCB];
    int i = blockIdx.x * SCB + threadIdx.x;
    int v = (i < n) ? g_cnt[i] : 0;
    sm[threadIdx.x] = v; __syncthreads();
    #pragma unroll
    for (int o = 1; o < SCB; o <<= 1) {
        int t = (threadIdx.x >= o) ? sm[threadIdx.x - o] : 0;
        __syncthreads(); sm[threadIdx.x] += t; __syncthreads();
    }
    if (i < n) g_rowstart[i] = sm[threadIdx.x] - v;
    if (threadIdx.x == SCB - 1) g_blksum[blockIdx.x] = sm[threadIdx.x];
}
__global__ void k_scan2(int nb) {
    __shared__ int sm[256];
    int v = (threadIdx.x < nb) ? g_blksum[threadIdx.x] : 0;
    sm[threadIdx.x] = v; __syncthreads();
    #pragma unroll
    for (int o = 1; o < 256; o <<= 1) {
        int t = (threadIdx.x >= o) ? sm[threadIdx.x - o] : 0;
        __syncthreads(); sm[threadIdx.x] += t; __syncthreads();
    }
    if (threadIdx.x < nb) g_blkoff[threadIdx.x] = sm[threadIdx.x] - v;
}
__global__ void k_scan3(int n, int E) {   // also computes inv-sqrt degrees
    int i = blockIdx.x * blockDim.x + threadIdx.x;
    if (i < n) {
        int r = g_rowstart[i] + g_blkoff[i / SCB];
        g_rowstart[i] = r;
        g_cursor[i]   = r;
        g_inv[i]      = rsqrtf((float)(1 + g_cnt[i]));
    }
    if (i == 0) g_rowstart[n] = E;
}
__global__ void k_fill(const int* __restrict__ src, const int* __restrict__ dst, int E) {
    int i = blockIdx.x * blockDim.x + threadIdx.x;
    if (i < E) {
        int pos = atomicAdd(&g_cursor[dst[i]], 1);
        g_esrc[pos] = src[i];
    }
}

// ---------------- fp16 mma m16n8k16 ----------------
__device__ __forceinline__ void mma_f16(float* c, uint32_t a0, uint32_t a1,
                                        uint32_t a2, uint32_t a3,
                                        uint32_t b0, uint32_t b1) {
    asm volatile(
        "mma.sync.aligned.m16n8k16.row.col.f32.f16.f16.f32 "
        "{%0,%1,%2,%3}, {%4,%5,%6,%7}, {%8,%9}, {%0,%1,%2,%3};"
        : "+f"(c[0]), "+f"(c[1]), "+f"(c[2]), "+f"(c[3])
        : "r"(a0), "r"(a1), "r"(a2), "r"(a3), "r"(b0), "r"(b1));
}

// ---- fp16 tensor-core GEMM, register-staged 2-stage pipeline ----
// A fp32 [M][K] row-major (converted to fp16 on the fly),
// Bt fp16 [BN][K] n-major (pre-transposed weights).
// LAYER==1: g_h1h = fp16( inv[row]*(x @ W1) )     (BN=128, K=512)
// LAYER==2: g_h2h = fp16( inv[row]*(a1 @ W2) )    (BN=64,  K=128)
template<int BM, int BN, int BK, int LAYER>
__global__ __launch_bounds__(256)
void k_mma(const float* __restrict__ Ain, int M, int K)
{
    constexpr int WARPS_N = BN / 64;      // 2 (L1) / 1 (L2)
    constexpr int WARPS_M = 8 / WARPS_N;  // 4 / 8
    constexpr int WM      = BM / WARPS_M; // 32 / 16
    constexpr int RT      = WM / 16;      // 2 / 1
    constexpr int KPAD    = BK + 8;       // 40 halves = 80B rows: conflict-free (20g+tg)
    constexpr int A_LD    = BM*BK/4/256;  // float4 loads per thread (A)
    constexpr int B_LD    = BN*BK/8/256;  // uint4 (8-half) loads per thread (B)

    __shared__ __half As[2][BM][KPAD];
    __shared__ __half Bs[2][BN][KPAD];

    const float*  A  = (LAYER == 1) ? Ain : (const float*)g_acc1;
    const __half* Bt = (LAYER == 1) ? (const __half*)g_W1t : (const __half*)g_W2t;
    __half*       G  = (LAYER == 1) ? (__half*)g_h1h : (__half*)g_h2h;
    const int     N  = BN;

    const int tid  = threadIdx.x;
    const int warp = tid >> 5;
    const int lane = tid & 31;
    const int g    = lane >> 2;
    const int tg   = lane & 3;
    const int wr   = (warp / WARPS_N) * WM;
    const int wc   = (warp % WARPS_N) * 64;
    const int rowBase = blockIdx.x * BM;

    float acc[RT][8][4] = {};
    float4 rA[A_LD];
    uint4  rB[B_LD];

    auto ldg_tiles = [&](int k0) {
        #pragma unroll
        for (int i = 0; i < A_LD; i++) {
            int id = tid + i*256;
            int m = id / (BK/4), k4 = id % (BK/4);
            int row = rowBase + m;
            rA[i] = (row < M) ? *(const float4*)(A + (size_t)row*K + k0 + k4*4)
                              : make_float4(0.f,0.f,0.f,0.f);
        }
        #pragma unroll
        for (int i = 0; i < B_LD; i++) {
            int id = tid + i*256;
            int n = id / (BK/8), c8 = id % (BK/8);
            rB[i] = *(const uint4*)(Bt + (size_t)n*K + k0 + c8*8);
        }
    };
    auto sts_tiles = [&](int st) {
        #pragma unroll
        for (int i = 0; i < A_LD; i++) {
            int id = tid + i*256;
            int m = id / (BK/4), k4 = id % (BK/4);
            __half2 p0 = __floats2half2_rn(rA[i].x, rA[i].y);
            __half2 p1 = __floats2half2_rn(rA[i].z, rA[i].w);
            uint2 u; u.x = *(uint32_t*)&p0; u.y = *(uint32_t*)&p1;
            *(uint2*)&As[st][m][k4*4] = u;
        }
        #pragma unroll
        for (int i = 0; i < B_LD; i++) {
            int id = tid + i*256;
            int n = id / (BK/8), c8 = id % (BK/8);
            *(uint4*)&Bs[st][n][c8*8] = rB[i];
        }
    };

    const int KT = K / BK;
    ldg_tiles(0);
    sts_tiles(0);
    if (KT > 1) ldg_tiles(BK);

    for (int kt = 0; kt < KT; kt++) {
        __syncthreads();                         // stage kt&1 visible; stage st^1 free
        const int st = kt & 1;
        if (kt + 1 < KT) sts_tiles(st ^ 1);      // regs hold tile kt+1
        if (kt + 2 < KT) ldg_tiles((kt+2)*BK);   // issue early, lands next iter
        #pragma unroll
        for (int ks = 0; ks < BK/16; ks++) {
            const int k = ks*16;
            uint32_t bf[8][2];
            #pragma unroll
            for (int j = 0; j < 8; j++) {
                bf[j][0] = *(const uint32_t*)&Bs[st][wc + j*8 + g][k + 2*tg];
                bf[j][1] = *(const uint32_t*)&Bs[st][wc + j*8 + g][k + 2*tg + 8];
            }
            #pragma unroll
            for (int rt = 0; rt < RT; rt++) {
                int r = wr + rt*16;
                uint32_t a0 = *(const uint32_t*)&As[st][r+g  ][k + 2*tg];
                uint32_t a1 = *(const uint32_t*)&As[st][r+g+8][k + 2*tg];
                uint32_t a2 = *(const uint32_t*)&As[st][r+g  ][k + 2*tg + 8];
                uint32_t a3 = *(const uint32_t*)&As[st][r+g+8][k + 2*tg + 8];
                #pragma unroll
                for (int j = 0; j < 8; j++)
                    mma_f16(acc[rt][j], a0, a1, a2, a3, bf[j][0], bf[j][1]);
            }
        }
    }

    #pragma unroll
    for (int rt = 0; rt < RT; rt++) {
        int r0 = rowBase + wr + rt*16 + g;
        int r1 = r0 + 8;
        float s0 = (r0 < M) ? g_inv[r0] : 0.f;
        float s1 = (r1 < M) ? g_inv[r1] : 0.f;
        #pragma unroll
        for (int j = 0; j < 8; j++) {
            int col = wc + j*8 + tg*2;
            if (r0 < M) {
                __half2 v = __floats2half2_rn(acc[rt][j][0]*s0, acc[rt][j][1]*s0);
                *(__half2*)(G + (size_t)r0*N + col) = v;
            }
            if (r1 < M) {
                __half2 v = __floats2half2_rn(acc[rt][j][2]*s1, acc[rt][j][3]*s1);
                *(__half2*)(G + (size_t)r1*N + col) = v;
            }
        }
    }
}

// ---------------- fp16 load helpers ----------------
__device__ __forceinline__ float4 ld_h4(const __half* p) {
    uint2 u = *(const uint2*)p;
    float2 a = __half22float2(*(__half2*)&u.x);
    float2 b = __half22float2(*(__half2*)&u.y);
    return make_float4(a.x, a.y, b.x, b.y);
}
__device__ __forceinline__ float2 ld_h2(const __half* p) {
    uint32_t u = *(const uint32_t*)p;
    return __half22float2(*(__half2*)&u);
}

// ---------------- gather layer 1: a1 = relu(inv*(g1[v] + sum g1[s]) + b1) ---
__global__ void k_gather1(const float* __restrict__ b1) {
    int w    = (blockIdx.x * blockDim.x + threadIdx.x) >> 5;
    int lane = threadIdx.x & 31;
    if (w >= N_NODES) return;
    const __half* h = (const __half*)g_h1h;
    float4 acc = ld_h4(h + (size_t)w*HID + lane*4);          // self-loop term
    int i   = g_rowstart[w];
    int end = g_rowstart[w+1];
    for (; i + 3 < end; i += 4) {
        int s0 = g_esrc[i],   s1 = g_esrc[i+1];
        int s2 = g_esrc[i+2], s3 = g_esrc[i+3];
        float4 v0 = ld_h4(h + (size_t)s0*HID + lane*4);
        float4 v1 = ld_h4(h + (size_t)s1*HID + lane*4);
        float4 v2 = ld_h4(h + (size_t)s2*HID + lane*4);
        float4 v3 = ld_h4(h + (size_t)s3*HID + lane*4);
        acc.x += (v0.x + v1.x) + (v2.x + v3.x);
        acc.y += (v0.y + v1.y) + (v2.y + v3.y);
        acc.z += (v0.z + v1.z) + (v2.z + v3.z);
        acc.w += (v0.w + v1.w) + (v2.w + v3.w);
    }
    for (; i < end; i++) {
        int s = g_esrc[i];
        float4 v = ld_h4(h + (size_t)s*HID + lane*4);
        acc.x += v.x; acc.y += v.y; acc.z += v.z; acc.w += v.w;
    }
    float sc = g_inv[w];
    float4 bb = *(const float4*)(b1 + lane*4);
    float4 o;
    o.x = fmaxf(fmaf(sc, acc.x, bb.x), 0.f);
    o.y = fmaxf(fmaf(sc, acc.y, bb.y), 0.f);
    o.z = fmaxf(fmaf(sc, acc.z, bb.z), 0.f);
    o.w = fmaxf(fmaf(sc, acc.w, bb.w), 0.f);
    *(float4*)((float*)g_acc1 + (size_t)w*HID + lane*4) = o;
}

// ---------------- gather layer 2 + log_softmax -> out ----------------------
__global__ void k_gather2(float* __restrict__ out, const float* __restrict__ b2) {
    int w    = (blockIdx.x * blockDim.x + threadIdx.x) >> 5;
    int lane = threadIdx.x & 31;
    if (w >= N_NODES) return;
    const __half* h = (const __half*)g_h2h;
    float2 acc = ld_h2(h + (size_t)w*CLS + lane*2);          // self-loop term
    int i   = g_rowstart[w];
    int end = g_rowstart[w+1];
    for (; i + 3 < end; i += 4) {
        int s0 = g_esrc[i],   s1 = g_esrc[i+1];
        int s2 = g_esrc[i+2], s3 = g_esrc[i+3];
        float2 v0 = ld_h2(h + (size_t)s0*CLS + lane*2);
        float2 v1 = ld_h2(h + (size_t)s1*CLS + lane*2);
        float2 v2 = ld_h2(h + (size_t)s2*CLS + lane*2);
        float2 v3 = ld_h2(h + (size_t)s3*CLS + lane*2);
        acc.x += (v0.x + v1.x) + (v2.x + v3.x);
        acc.y += (v0.y + v1.y) + (v2.y + v3.y);
    }
    for (; i < end; i++) {
        int s = g_esrc[i];
        float2 v = ld_h2(h + (size_t)s*CLS + lane*2);
        acc.x += v.x; acc.y += v.y;
    }
    float sc = g_inv[w];
    float t0 = fmaf(sc, acc.x, b2[lane*2+0]);
    float t1 = fmaf(sc, acc.y, b2[lane*2+1]);
    float m = fmaxf(t0, t1);
    #pragma unroll
    for (int o = 16; o > 0; o >>= 1) m = fmaxf(m, __shfl_xor_sync(0xffffffffu, m, o));
    float sum = __expf(t0 - m) + __expf(t1 - m);
    #pragma unroll
    for (int o = 16; o > 0; o >>= 1) sum += __shfl_xor_sync(0xffffffffu, sum, o);
    float ls = m + __logf(sum);
    float2 r; r.x = t0 - ls; r.y = t1 - ls;
    *(float2*)(out + (size_t)w*CLS + lane*2) = r;
}

// ---------------- launch ----------------
extern "C" void kernel_launch(void* const* d_in, const int* in_sizes, int n_in,
                              void* d_out, int out_size)
{
    const float* x   = (const float*)d_in[0];
    const int*   src = (const int*)d_in[1];     // int32 (JAX x64 disabled)
    const int*   dst = (const int*)d_in[2];
    const float* W1  = (const float*)d_in[3];
    const float* b1  = (const float*)d_in[4];
    const float* W2  = (const float*)d_in[5];
    const float* b2  = (const float*)d_in[6];
    float* out = (float*)d_out;
    const int E = in_sizes[1];

    const int nb256 = (N_NODES + 255)/256;
    const int eb256 = (E + 255)/256;
    const int sb    = (N_NODES + SCB - 1)/SCB;
    const int gx    = (N_NODES + 127)/128;
    const int gwarp = (N_NODES*32 + 255)/256;

    // one-time weight transpose + fp16 convert
    k_prepw<<<(HID*F_IN + 255)/256, 256>>>(W1, W2);

    // CSR-by-dst build + normalization
    k_zero <<<nb256, 256>>>();
    k_hist <<<eb256, 256>>>(dst, E);
    k_scan1<<<sb, SCB>>>(N_NODES);
    k_scan2<<<1, 256>>>(sb);
    k_scan3<<<sb, SCB>>>(N_NODES, E);
    k_fill <<<eb256, 256>>>(src, dst, E);

    // layer 1
    k_mma<128,128,32,1><<<gx, 256>>>(x, N_NODES, F_IN);
    k_gather1<<<gwarp, 256>>>(b1);

    // layer 2
    k_mma<128,64,32,2><<<gx, 256>>>(nullptr, N_NODES, HID);
    k_gather2<<<gwarp, 256>>>(out, b2);
}